// round 11
// baseline (speedup 1.0000x reference)
#include <cuda_runtime.h>

#define HIDDEN   64
#define NTHREADS 128     // thread = (unit j, batch m); 2 batches per CTA

// ---------- packed f32x2 helpers ----------
__device__ __forceinline__ unsigned long long ffma2(unsigned long long a,
                                                    unsigned long long b,
                                                    unsigned long long c) {
    unsigned long long d;
    asm("fma.rn.f32x2 %0, %1, %2, %3;" : "=l"(d) : "l"(a), "l"(b), "l"(c));
    return d;
}
__device__ __forceinline__ unsigned long long fadd2(unsigned long long a,
                                                    unsigned long long b) {
    unsigned long long d;
    asm("add.rn.f32x2 %0, %1, %2;" : "=l"(d) : "l"(a), "l"(b));
    return d;
}
__device__ __forceinline__ unsigned long long pack2(float lo, float hi) {
    unsigned long long r;
    asm("mov.b64 %0, {%1, %2};" : "=l"(r) : "f"(lo), "f"(hi));
    return r;
}
__device__ __forceinline__ float2 unpack2(unsigned long long v) {
    float2 r;
    asm("mov.b64 {%0, %1}, %2;" : "=f"(r.x), "=f"(r.y) : "l"(v));
    return r;
}
__device__ __forceinline__ float tanh_approx(float x) {   // 1 MUFU
    float r; asm("tanh.approx.f32 %0, %1;" : "=f"(r) : "f"(x)); return r;
}

struct GruConsts {
    float wr_h, br_h, wz_h, bz_h, wn, bihn, bhhn;
};

// full 64-length dot: 32 packed FFMA2, 4 independent chains
__device__ __forceinline__ float full_dot(const unsigned long long* wg_,
                                          const unsigned long long* hv) {
    unsigned long long q0 = ffma2(wg_[0], hv[0], 0ull);
    unsigned long long q1 = ffma2(wg_[1], hv[1], 0ull);
    unsigned long long q2 = ffma2(wg_[2], hv[2], 0ull);
    unsigned long long q3 = ffma2(wg_[3], hv[3], 0ull);
    #pragma unroll
    for (int i = 1; i < 8; i++) {
        q0 = ffma2(wg_[4 * i],     hv[4 * i],     q0);
        q1 = ffma2(wg_[4 * i + 1], hv[4 * i + 1], q1);
        q2 = ffma2(wg_[4 * i + 2], hv[4 * i + 2], q2);
        q3 = ffma2(wg_[4 * i + 3], hv[4 * i + 3], q3);
    }
    float2 sp = unpack2(fadd2(fadd2(q0, q1), fadd2(q2, q3)));
    return sp.x + sp.y;
}

// one GRU timestep, fully in-thread after the h load (no shfl, no reduction)
__device__ __forceinline__ void gru_step(float xv,
                                         const float* __restrict__ hin,
                                         float* __restrict__ hout,
                                         const unsigned long long (*wreg)[32],
                                         const GruConsts& c,
                                         float& h_old,
                                         int j)
{
    // x-terms (independent of h)
    float arh = fmaf(xv, c.wr_h, c.br_h);
    float azh = fmaf(xv, c.wz_h, c.bz_h);
    float ain = fmaf(xv, c.wn,   c.bihn);

    // load all 64 h once (8 LDS.128 broadcast), reuse for 3 gates
    unsigned long long hv[32];
    const ulonglong2* h2 = reinterpret_cast<const ulonglong2*>(hin);
    #pragma unroll
    for (int i = 0; i < 8; i++) {
        ulonglong2 v = h2[i];
        hv[4 * i]     = v.x;            // careful: ulonglong2 = 16B = 2 packed
        hv[4 * i + 1] = v.y;
    }
    // note: 8 ulonglong2 loads give 16 packed values; load the other 16 too
    const ulonglong2* h2b = h2 + 8;
    #pragma unroll
    for (int i = 0; i < 8; i++) {
        ulonglong2 v = h2b[i];
        hv[4 * i + 2] = v.x;
        hv[4 * i + 3] = v.y;
    }

    // ---- r gate first: its MUFU overlaps the n-dot issue ----
    float dr = full_dot(wreg[0], hv);
    float taur = tanh_approx(fmaf(0.5f, dr, arh));

    // ---- n gate second: nval MUFU overlaps the z-dot issue ----
    float dn = full_dot(wreg[2], hv);
    float dnb  = dn + c.bhhn;
    float nval = tanh_approx(fmaf(taur, 0.5f * dnb, fmaf(0.5f, dnb, ain)));

    // ---- z gate last ----
    float dz = full_dot(wreg[1], hv);
    float tauz = tanh_approx(fmaf(0.5f, dz, azh));

    float dd = h_old - nval;                       // h = n + z*(h-n)
    h_old = fmaf(tauz, 0.5f * dd, fmaf(0.5f, dd, nval));

    hout[j] = h_old;
    __syncthreads();
}

__global__ void __launch_bounds__(NTHREADS, 1)
gru_scan_kernel(const float* __restrict__ x,
                const float* __restrict__ W_ih,
                const float* __restrict__ W_hh,
                const float* __restrict__ b_ih,
                const float* __restrict__ b_hh,
                const float* __restrict__ W_fc,
                const float* __restrict__ b_fc,
                float* __restrict__ out,
                int Btotal, int T)
{
    __shared__ __align__(16) float h_sh[2][2][HIDDEN];   // [parity][batch][j]
    __shared__ float red_sh[2][2];

    const int tid  = threadIdx.x;
    const int m    = tid / HIDDEN;             // batch slot: warps 0,1 | 2,3
    const int j    = tid % HIDDEN;             // hidden unit (one per thread)
    const int lane = tid % 32;
    const int b    = blockIdx.x * 2 + m;

    // ---- 3 full gate rows in registers: 3 x 32 packed f32x2 (96 regs) ----
    unsigned long long wreg[3][32];
    #pragma unroll
    for (int g = 0; g < 3; g++) {
        const float4* row = reinterpret_cast<const float4*>(
            W_hh + (g * HIDDEN + j) * HIDDEN);
        #pragma unroll
        for (int i = 0; i < 16; i++) {
            float4 v = row[i];
            // interleave to match gru_step's hv layout:
            // hv[4i],hv[4i+1] from first 32 floats; hv[4i+2],hv[4i+3] from last 32
            int k4 = i < 8 ? (4 * i)     : (4 * (i - 8) + 2);
            wreg[g][k4]     = pack2(v.x, v.y);
            wreg[g][k4 + 1] = pack2(v.z, v.w);
        }
    }

    GruConsts c;
    c.wr_h = 0.5f * W_ih[j];
    c.br_h = 0.5f * (b_ih[j] + b_hh[j]);
    c.wz_h = 0.5f * W_ih[HIDDEN + j];
    c.bz_h = 0.5f * (b_ih[HIDDEN + j] + b_hh[HIDDEN + j]);
    c.wn   = W_ih[2 * HIDDEN + j];
    c.bihn = b_ih[2 * HIDDEN + j];
    c.bhhn = b_hh[2 * HIDDEN + j];
    const float wfc = W_fc[j];
    const float bfc = __ldg(b_fc);

    const float* xb = x + (size_t)((b < Btotal) ? b : 0) * T;
    float h_old = 0.0f;
    h_sh[0][m][j] = 0.0f;
    __syncthreads();

    // T even (3000): unroll by 2 with static ping-pong buffers
    float2 xq = *reinterpret_cast<const float2*>(xb);
    const int Teven = T & ~1;
    for (int t = 0; t < Teven; t += 2) {
        int tn = t + 2;
        if (tn > Teven - 2) tn = Teven - 2;
        float2 xq_next = *reinterpret_cast<const float2*>(xb + tn);

        gru_step(xq.x, h_sh[0][m], h_sh[1][m], wreg, c, h_old, j);
        gru_step(xq.y, h_sh[1][m], h_sh[0][m], wreg, c, h_old, j);

        xq = xq_next;
    }
    if (Teven != T) {
        float xv = __ldg(xb + Teven);
        gru_step(xv, h_sh[0][m], h_sh[1][m], wreg, c, h_old, j);
    }

    // ---- out[b] = h . W_fc + b_fc : reduce 64 per-unit products ----
    float v = h_old * wfc;
    #pragma unroll
    for (int o = 16; o > 0; o >>= 1)
        v += __shfl_xor_sync(0xffffffffu, v, o);
    if (lane == 0) red_sh[m][(tid / 32) & 1] = v;
    __syncthreads();
    if (j == 0 && b < Btotal) {
        out[b] = red_sh[m][0] + red_sh[m][1] + bfc;
    }
}

extern "C" void kernel_launch(void* const* d_in, const int* in_sizes, int n_in,
                              void* d_out, int out_size)
{
    const float* x    = (const float*)d_in[0];
    const float* W_ih = (const float*)d_in[1];
    const float* W_hh = (const float*)d_in[2];
    const float* b_ih = (const float*)d_in[3];
    const float* b_hh = (const float*)d_in[4];
    const float* W_fc = (const float*)d_in[5];
    const float* b_fc = (const float*)d_in[6];

    int B = out_size;                 // 256
    int T = in_sizes[0] / B;          // 3000
    int grid = (B + 1) / 2;           // 128 CTAs -> 1 per SM

    gru_scan_kernel<<<grid, NTHREADS>>>(x, W_ih, W_hh, b_ih, b_hh, W_fc, b_fc,
                                        (float*)d_out, B, T);
}

// round 12
// speedup vs baseline: 1.3457x; 1.3457x over previous
#include <cuda_runtime.h>

#define HIDDEN   64
#define NTHREADS 128     // one batch element per CTA; thread = (unit j, k-half)

// ---------- packed f32x2 helpers ----------
__device__ __forceinline__ unsigned long long ffma2(unsigned long long a,
                                                    unsigned long long b,
                                                    unsigned long long c) {
    unsigned long long d;
    asm("fma.rn.f32x2 %0, %1, %2, %3;" : "=l"(d) : "l"(a), "l"(b), "l"(c));
    return d;
}
__device__ __forceinline__ unsigned long long fadd2(unsigned long long a,
                                                    unsigned long long b) {
    unsigned long long d;
    asm("add.rn.f32x2 %0, %1, %2;" : "=l"(d) : "l"(a), "l"(b));
    return d;
}
__device__ __forceinline__ unsigned long long pack2(float lo, float hi) {
    unsigned long long r;
    asm("mov.b64 %0, {%1, %2};" : "=l"(r) : "f"(lo), "f"(hi));
    return r;
}
__device__ __forceinline__ float2 unpack2(unsigned long long v) {
    float2 r;
    asm("mov.b64 {%0, %1}, %2;" : "=f"(r.x), "=f"(r.y) : "l"(v));
    return r;
}
__device__ __forceinline__ float tanh_approx(float x) {   // 1 MUFU
    float r; asm("tanh.approx.f32 %0, %1;" : "=f"(r) : "f"(x)); return r;
}

struct GruConsts {
    float wr_h, br_h, wz_h, bz_h, wn, bihn, bhhn_h;
};

// 16 packed FFMA2 over one (pre-halved) gate half-row, 4 chains
__device__ __forceinline__ float half_dot(const unsigned long long* wg_,
                                          const unsigned long long* hv) {
    unsigned long long q0 = ffma2(wg_[0], hv[0], 0ull);
    unsigned long long q1 = ffma2(wg_[1], hv[1], 0ull);
    unsigned long long q2 = ffma2(wg_[2], hv[2], 0ull);
    unsigned long long q3 = ffma2(wg_[3], hv[3], 0ull);
    #pragma unroll
    for (int i = 1; i < 4; i++) {
        q0 = ffma2(wg_[4 * i],     hv[4 * i],     q0);
        q1 = ffma2(wg_[4 * i + 1], hv[4 * i + 1], q1);
        q2 = ffma2(wg_[4 * i + 2], hv[4 * i + 2], q2);
        q3 = ffma2(wg_[4 * i + 3], hv[4 * i + 3], q3);
    }
    float2 sp = unpack2(fadd2(fadd2(q0, q1), fadd2(q2, q3)));
    return sp.x + sp.y;
}

// one GRU timestep. Gate order z, r, n: z/r reduction tails hide under the
// following gate's dot issue; only n's tail (which feeds h) stays on-chain.
// Weight rows are pre-scaled by 0.5 at load (tanh-sigmoid identity + n-arg fold).
__device__ __forceinline__ void gru_step(float xv,
                                         const float* __restrict__ hin,
                                         float* __restrict__ hout,
                                         const unsigned long long (*wreg)[16],
                                         const GruConsts& c,
                                         float& h_old,
                                         int half, int j)
{
    // x-terms (independent of h)
    float azh = fmaf(xv, c.wz_h, c.bz_h);
    float arh = fmaf(xv, c.wr_h, c.br_h);
    float ain = fmaf(xv, c.wn,   c.bihn);

    // load my k-half of h once (8 LDS.128 broadcast), reuse for 3 gates
    unsigned long long hv[16];
    const ulonglong2* h2 = reinterpret_cast<const ulonglong2*>(hin + half * 32);
    #pragma unroll
    for (int i = 0; i < 8; i++) {
        ulonglong2 v = h2[i];
        hv[2 * i]     = v.x;
        hv[2 * i + 1] = v.y;
    }

    // ---- z first: its shfl+MUFU hide under the r-dot issue ----
    float dz = half_dot(wreg[1], hv);                  // pre-halved
    dz += __shfl_xor_sync(0xffffffffu, dz, 16);
    float tauz = tanh_approx(dz + azh);

    // ---- r second: taur MUFU hides under the n-dot issue ----
    float dr = half_dot(wreg[0], hv);                  // pre-halved
    dr += __shfl_xor_sync(0xffffffffu, dr, 16);
    float taur = tanh_approx(dr + arh);

    // ---- n last: only this tail is on the serial chain ----
    float dnh = half_dot(wreg[2], hv);                 // pre-halved
    dnh += __shfl_xor_sync(0xffffffffu, dnh, 16);
    float dnb  = dnh + c.bhhn_h;                       // = 0.5*(dot_n + b_hh_n)
    float nval = tanh_approx(fmaf(taur, dnb, dnb + ain));

    float dd = h_old - nval;                           // h = n + z*(h-n)
    h_old = fmaf(tauz, 0.5f * dd, fmaf(0.5f, dd, nval));

    if (half == 0) hout[j] = h_old;
    __syncthreads();
}

__global__ void __launch_bounds__(NTHREADS, 2)
gru_scan_kernel(const float* __restrict__ x,
                const float* __restrict__ W_ih,
                const float* __restrict__ W_hh,
                const float* __restrict__ b_ih,
                const float* __restrict__ b_hh,
                const float* __restrict__ W_fc,
                const float* __restrict__ b_fc,
                float* __restrict__ out,
                int Btotal, int T)
{
    __shared__ __align__(16) float h_sh[2][HIDDEN];   // ping-pong by parity
    __shared__ float red_sh[4];

    const int tid  = threadIdx.x;
    const int wg   = tid / 32;                 // warp 0..3
    const int lane = tid % 32;
    const int j    = wg * 16 + (lane & 15);    // hidden unit
    const int half = lane >> 4;                // k-half; partner = lane^16
    const int b    = blockIdx.x;               // one batch per CTA

    // ---- 3 gate half-rows in registers, PRE-SCALED by 0.5 (96 regs) ----
    unsigned long long wreg[3][16];
    #pragma unroll
    for (int g = 0; g < 3; g++) {
        const float4* row = reinterpret_cast<const float4*>(
            W_hh + (g * HIDDEN + j) * HIDDEN + half * 32);
        #pragma unroll
        for (int i = 0; i < 8; i++) {
            float4 v = row[i];
            wreg[g][2 * i]     = pack2(0.5f * v.x, 0.5f * v.y);
            wreg[g][2 * i + 1] = pack2(0.5f * v.z, 0.5f * v.w);
        }
    }

    GruConsts c;
    c.wr_h   = 0.5f * W_ih[j];
    c.br_h   = 0.5f * (b_ih[j] + b_hh[j]);
    c.wz_h   = 0.5f * W_ih[HIDDEN + j];
    c.bz_h   = 0.5f * (b_ih[HIDDEN + j] + b_hh[HIDDEN + j]);
    c.wn     = W_ih[2 * HIDDEN + j];
    c.bihn   = b_ih[2 * HIDDEN + j];
    c.bhhn_h = 0.5f * b_hh[2 * HIDDEN + j];
    const float wfc = W_fc[j];
    const float bfc = __ldg(b_fc);

    const float* xb = x + (size_t)b * T;
    float h_old = 0.0f;
    if (half == 0) h_sh[0][j] = 0.0f;
    __syncthreads();

    // main loop: unroll x4, float4 x loads, no per-iter clamping
    const int Tmain = T & ~3;                  // 3000 -> 3000
    if (Tmain >= 4) {
        float4 xq = *reinterpret_cast<const float4*>(xb);
        for (int t = 0; t < Tmain; t += 4) {
            int tn = t + 4;
            if (tn > Tmain - 4) tn = Tmain - 4;
            float4 xq_next = *reinterpret_cast<const float4*>(xb + tn);

            gru_step(xq.x, h_sh[0], h_sh[1], wreg, c, h_old, half, j);
            gru_step(xq.y, h_sh[1], h_sh[0], wreg, c, h_old, half, j);
            gru_step(xq.z, h_sh[0], h_sh[1], wreg, c, h_old, half, j);
            gru_step(xq.w, h_sh[1], h_sh[0], wreg, c, h_old, half, j);

            xq = xq_next;
        }
    }
    // tail (0..3 steps; not hit for T=3000)
    {
        float* hb[2] = { h_sh[0], h_sh[1] };
        int p = 0;
        for (int t = Tmain; t < T; t++) {
            float xv = __ldg(xb + t);
            gru_step(xv, hb[p], hb[p ^ 1], wreg, c, h_old, half, j);
            p ^= 1;
        }
    }

    // ---- out[b] = h . W_fc + b_fc (h identical in both halves' regs) ----
    float v = (half == 0) ? h_old * wfc : 0.0f;
    #pragma unroll
    for (int o = 16; o > 0; o >>= 1)
        v += __shfl_xor_sync(0xffffffffu, v, o);
    if (lane == 0) red_sh[wg] = v;
    __syncthreads();
    if (tid == 0) {
        out[b] = red_sh[0] + red_sh[1] + red_sh[2] + red_sh[3] + bfc;
    }
}

extern "C" void kernel_launch(void* const* d_in, const int* in_sizes, int n_in,
                              void* d_out, int out_size)
{
    const float* x    = (const float*)d_in[0];
    const float* W_ih = (const float*)d_in[1];
    const float* W_hh = (const float*)d_in[2];
    const float* b_ih = (const float*)d_in[3];
    const float* b_hh = (const float*)d_in[4];
    const float* W_fc = (const float*)d_in[5];
    const float* b_fc = (const float*)d_in[6];

    int B = out_size;                 // 256
    int T = in_sizes[0] / B;          // 3000

    gru_scan_kernel<<<B, NTHREADS>>>(x, W_ih, W_hh, b_ih, b_hh, W_fc, b_fc,
                                     (float*)d_out, B, T);
}